// round 4
// baseline (speedup 1.0000x reference)
#include <cuda_runtime.h>
#include <math.h>

// ---------------- constants ----------------
#define PADK         68        // padded column stride (floats) -> conflict-free LDS.128
#define OFF_W0T      0
#define OFF_W1T      2176
#define OFF_W2T      4352
#define OFF_W3T      6528
#define OFF_WAT      8704
#define OFF_WBT      10880
#define OFF_WM1T     13056
#define OFF_WM2T     17408
#define OFF_WM3T     21760
#define WTOT         30464     // total weight floats in smem
#define NWARP        8
#define NPAIR        4         // row-pairs per warp (8 rows)
#define RS2          768       // floats per row-PAIR (interleaved)
// pair-local float offsets (each logical element is 2 floats: {rowA,rowB})
#define PS0          0         // s0: 64 elems  -> overlay m0
#define PS1          128       // s1: 192 elems ([k][u], k stride 128 floats) -> overlay m1
#define PT1          512       // t1: 64 elems  -> overlay ob (rowA at PT1, rowB at PT1+128)
#define PHB          640       // sc then hb: 64 elems
#define SMEM_FLOATS  (WTOT + NWARP * NPAIR * RS2)   // 30464 + 24576 = 55040
#define SMEM_BYTES   (SMEM_FLOATS * 4)              // 220160

__device__ float g_cst;
__device__ float g_wbuf[WTOT];

// ---------------- packed f32x2 helpers ----------------
typedef unsigned long long u64;
__device__ __forceinline__ u64 pk2(float lo, float hi) {
    u64 d; asm("mov.b64 %0,{%1,%2};" : "=l"(d) : "f"(lo), "f"(hi)); return d;
}
__device__ __forceinline__ u64 dup2(float w) {
    u64 d; asm("mov.b64 %0,{%1,%1};" : "=l"(d) : "f"(w)); return d;
}
__device__ __forceinline__ u64 f2fma(u64 a, u64 b, u64 c) {
    u64 d; asm("fma.rn.f32x2 %0,%1,%2,%3;" : "=l"(d) : "l"(a), "l"(b), "l"(c)); return d;
}
__device__ __forceinline__ u64 f2mul(u64 a, u64 b) {
    u64 d; asm("mul.rn.f32x2 %0,%1,%2;" : "=l"(d) : "l"(a), "l"(b)); return d;
}
__device__ __forceinline__ void upk2(u64 v, float& lo, float& hi) {
    asm("mov.b64 {%0,%1},%2;" : "=f"(lo), "=f"(hi) : "l"(v));
}

#define DUP4(nm, v4) u64 nm##x = dup2((v4).x), nm##y = dup2((v4).y), \
                         nm##z = dup2((v4).z), nm##w = dup2((v4).w)
#define FMA4(acc, t0, t1, W) do { \
    acc = f2fma((t0).x, W##x, acc); acc = f2fma((t0).y, W##y, acc); \
    acc = f2fma((t1).x, W##z, acc); acc = f2fma((t1).y, W##w, acc); } while (0)

// ---------------- prep: cst (block 0) + fold scales, merge Wl@Wf, transpose+pad ----------
__global__ void prep_kernel(const float* __restrict__ w0, const float* __restrict__ w1,
                            const float* __restrict__ w2, const float* __restrict__ w3,
                            const float* __restrict__ Wl0, const float* __restrict__ Wl1,
                            const float* __restrict__ Wm1, const float* __restrict__ Wm2,
                            const float* __restrict__ Wm3,
                            const float* __restrict__ Wf0, const float* __restrict__ Wf1) {
    if (blockIdx.x == 0) {
        const int   N = 20000;
        const float h = 24.0f / 20000.0f;
        float local = 0.0f;
        for (int i = threadIdx.x; i <= N; i += blockDim.x) {
            float z   = -12.0f + h * (float)i;
            float s   = z / (1.0f + __expf(-z));
            float phi = __expf(-0.5f * z * z) * 0.3989422804014327f;
            float f   = s * s * phi;
            if (i == 0 || i == N) f *= 0.5f;
            local += f;
        }
        __shared__ float red[256];
        red[threadIdx.x] = local;
        __syncthreads();
        for (int s = 128; s > 0; s >>= 1) {
            if (threadIdx.x < s) red[threadIdx.x] += red[threadIdx.x + s];
            __syncthreads();
        }
        if (threadIdx.x == 0) g_cst = rsqrtf(red[0] * h);
    }

    int tid = blockIdx.x * blockDim.x + threadIdx.x;
    if (tid >= 28672) return;
    const float INV_S3 = 0.57735026918962576f;
    const float WSCALE = 0.125f * 0.125f * 0.17677669529663687f;  // PW/(sqrt(U)*sqrt(MUL))

    if (tid < 12288) {                       // six (64,32) matrices
        int m = tid / 2048, r = tid % 2048;
        int i = r / 32, j = r % 32;
        float v; int off;
        if (m == 0)      { v = w0[i * 32 + j];           off = OFF_W0T; }
        else if (m == 1) { v = w1[i * 32 + j] * INV_S3;  off = OFF_W1T; }
        else if (m == 2) { v = w2[i * 32 + j];           off = OFF_W2T; }
        else if (m == 3) { v = w3[i * 32 + j];           off = OFF_W3T; }
        else {
            const float* L = (m == 4) ? Wl0 : Wl1;
            const float* F = (m == 4) ? Wf0 : Wf1;
            float acc = 0.0f;
            for (int w = 0; w < 32; w++) acc = fmaf(L[i * 32 + w], F[w * 32 + j], acc);
            v   = acc * WSCALE;
            off = (m == 4) ? OFF_WAT : OFF_WBT;
        }
        g_wbuf[off + j * PADK + i] = v;
    } else if (tid < 20480) {                // Wm1 / Wm2 (64,64), fold 1/8
        int t2 = tid - 12288;
        int mm = t2 / 4096, r = t2 % 4096;
        int i = r / 64, j = r % 64;
        const float* W = mm ? Wm2 : Wm1;
        g_wbuf[(mm ? OFF_WM2T : OFF_WM1T) + j * PADK + i] = W[i * 64 + j] * 0.125f;
    } else {                                 // Wm3 (64,128), fold 1/8
        int r = tid - 20480;
        int i = r / 128, j = r % 128;
        g_wbuf[OFF_WM3T + j * PADK + i] = Wm3[i * 128 + j] * 0.125f;
    }
}

// ---------------- main: warp = 4 row-pairs (8 rows), f32x2 packed math ----------------
__global__ __launch_bounds__(256, 1)
void tp_main_kernel(const float* __restrict__ x1a, const float* __restrict__ x1b,
                    const float4* __restrict__ x2, const float* __restrict__ scalars,
                    float* __restrict__ out, int nrows) {
    extern __shared__ float smem[];
    {
        const float4* src = (const float4*)g_wbuf;
        float4* dst = (float4*)smem;
        for (int i = threadIdx.x; i < WTOT / 4; i += blockDim.x) dst[i] = src[i];
    }
    __syncthreads();
    const float cst = g_cst;

    const int lid = threadIdx.x & 31;
    const int wid = threadIdx.x >> 5;

    float* Sw = smem + WTOT + wid * (NPAIR * RS2);

    const float* w0t  = smem + OFF_W0T;
    const float* w1t  = smem + OFF_W1T;
    const float* w2t  = smem + OFF_W2T;
    const float* w3t  = smem + OFF_W3T;
    const float* wat  = smem + OFF_WAT;
    const float* wbt  = smem + OFF_WBT;
    const float* wm1t = smem + OFF_WM1T;
    const float* wm2t = smem + OFF_WM2T;
    const float* wm3t = smem + OFF_WM3T;

    const int gstride = gridDim.x * NWARP * (2 * NPAIR);
    for (int e = (blockIdx.x * NWARP + wid) * (2 * NPAIR); e < nrows; e += gstride) {
        // ---- stage 8 rows (4 interleaved pairs); nrows % 8 == 0 ----
        float4 yv4[2 * NPAIR];
#pragma unroll
        for (int r = 0; r < 2 * NPAIR; r++) {
            int row = e + r;
            float* P = Sw + (r >> 1) * RS2;
            int h = r & 1;
            float4 va = ((const float4*)x1a)[row * 32 + lid];
            float4 vb = ((const float4*)x1b)[row * 32 + lid];
            yv4[r] = x2[row];
            if (lid < 16) {
                float4 s = ((const float4*)scalars)[row * 16 + lid];
                int b0 = PHB + 8 * lid + h;
                P[b0] = s.x; P[b0 + 2] = s.y; P[b0 + 4] = s.z; P[b0 + 6] = s.w;
            }
            if (lid < 8) {
                int b0 = PS0 + 8 * lid + h;
                P[b0] = va.x; P[b0 + 2] = va.y; P[b0 + 4] = va.z; P[b0 + 6] = va.w;
                int b1 = PS0 + 64 + 8 * lid + h;
                P[b1] = vb.x; P[b1 + 2] = vb.y; P[b1 + 4] = vb.z; P[b1 + 6] = vb.w;
            } else {
                int f = 4 * lid - 32;
                float av[4] = {va.x, va.y, va.z, va.w};
                float bv[4] = {vb.x, vb.y, vb.z, vb.w};
#pragma unroll
                for (int t = 0; t < 4; t++) {
                    int u = (f + t) / 3, k = (f + t) % 3;
                    P[PS1 + k * 128 + 2 * u + h]      = av[t];
                    P[PS1 + k * 128 + 64 + 2 * u + h] = bv[t];
                }
            }
        }
        __syncwarp();

        // ---- t1[u] = s1[u,:] . y1 (packed; Y packs recomputed on demand) ----
#pragma unroll
        for (int p = 0; p < NPAIR; p++) {
            float* P = Sw + p * RS2;
            u64 Y1 = pk2(yv4[2 * p].y, yv4[2 * p + 1].y);
            u64 Y2 = pk2(yv4[2 * p].z, yv4[2 * p + 1].z);
            u64 Y3 = pk2(yv4[2 * p].w, yv4[2 * p + 1].w);
            u64 a = f2mul(*(const u64*)&P[PS1 + 2 * lid], Y1);
            a = f2fma(*(const u64*)&P[PS1 + 128 + 2 * lid], Y2, a);
            a = f2fma(*(const u64*)&P[PS1 + 256 + 2 * lid], Y3, a);
            *(u64*)&P[PT1 + 2 * lid] = a;
            u64 b = f2mul(*(const u64*)&P[PS1 + 64 + 2 * lid], Y1);
            b = f2fma(*(const u64*)&P[PS1 + 192 + 2 * lid], Y2, b);
            b = f2fma(*(const u64*)&P[PS1 + 320 + 2 * lid], Y3, b);
            *(u64*)&P[PT1 + 64 + 2 * lid] = b;
        }

        // ---- MLP layer 1 ----
        {
            u64 a0[NPAIR] = {0, 0, 0, 0}, a1[NPAIR] = {0, 0, 0, 0};
#pragma unroll
            for (int i = 0; i < 64; i += 4) {
                float4 wa = *(const float4*)&wm1t[lid * PADK + i];
                float4 wb = *(const float4*)&wm1t[(lid + 32) * PADK + i];
                DUP4(WA, wa); DUP4(WB, wb);
#pragma unroll
                for (int p = 0; p < NPAIR; p++) {
                    const float* P = Sw + p * RS2;
                    ulonglong2 t0 = *(const ulonglong2*)&P[PHB + 2 * i];
                    ulonglong2 t1 = *(const ulonglong2*)&P[PHB + 2 * i + 4];
                    FMA4(a0[p], t0, t1, WA);
                    FMA4(a1[p], t0, t1, WB);
                }
            }
            __syncwarp();
#pragma unroll
            for (int p = 0; p < NPAIR; p++) {
                float* P = Sw + p * RS2;
                float l0, h0, l1, h1;
                upk2(a0[p], l0, h0); upk2(a1[p], l1, h1);
                l0 = cst * l0 / (1.0f + __expf(-l0)); h0 = cst * h0 / (1.0f + __expf(-h0));
                l1 = cst * l1 / (1.0f + __expf(-l1)); h1 = cst * h1 / (1.0f + __expf(-h1));
                *(u64*)&P[PHB + 2 * lid]      = pk2(l0, h0);
                *(u64*)&P[PHB + 64 + 2 * lid] = pk2(l1, h1);
            }
            __syncwarp();
        }

        // ---- MLP layer 2 ----
        {
            u64 a0[NPAIR] = {0, 0, 0, 0}, a1[NPAIR] = {0, 0, 0, 0};
#pragma unroll
            for (int i = 0; i < 64; i += 4) {
                float4 wa = *(const float4*)&wm2t[lid * PADK + i];
                float4 wb = *(const float4*)&wm2t[(lid + 32) * PADK + i];
                DUP4(WA, wa); DUP4(WB, wb);
#pragma unroll
                for (int p = 0; p < NPAIR; p++) {
                    const float* P = Sw + p * RS2;
                    ulonglong2 t0 = *(const ulonglong2*)&P[PHB + 2 * i];
                    ulonglong2 t1 = *(const ulonglong2*)&P[PHB + 2 * i + 4];
                    FMA4(a0[p], t0, t1, WA);
                    FMA4(a1[p], t0, t1, WB);
                }
            }
            __syncwarp();
#pragma unroll
            for (int p = 0; p < NPAIR; p++) {
                float* P = Sw + p * RS2;
                float l0, h0, l1, h1;
                upk2(a0[p], l0, h0); upk2(a1[p], l1, h1);
                l0 = cst * l0 / (1.0f + __expf(-l0)); h0 = cst * h0 / (1.0f + __expf(-h0));
                l1 = cst * l1 / (1.0f + __expf(-l1)); h1 = cst * h1 / (1.0f + __expf(-h1));
                *(u64*)&P[PHB + 2 * lid]      = pk2(l0, h0);
                *(u64*)&P[PHB + 64 + 2 * lid] = pk2(l1, h1);
            }
            __syncwarp();
        }

        // ---- MLP layer 3: weights[128] kept in registers (same-lane use only) ----
        u64 b0[NPAIR] = {0, 0, 0, 0}, b1[NPAIR] = {0, 0, 0, 0},
            b2[NPAIR] = {0, 0, 0, 0}, b3[NPAIR] = {0, 0, 0, 0};
#pragma unroll
        for (int i = 0; i < 64; i += 4) {
            float4 wv0 = *(const float4*)&wm3t[lid * PADK + i];
            float4 wv1 = *(const float4*)&wm3t[(lid + 32) * PADK + i];
            float4 wv2 = *(const float4*)&wm3t[(lid + 64) * PADK + i];
            float4 wv3 = *(const float4*)&wm3t[(lid + 96) * PADK + i];
            DUP4(W0, wv0); DUP4(W1, wv1); DUP4(W2, wv2); DUP4(W3, wv3);
#pragma unroll
            for (int p = 0; p < NPAIR; p++) {
                const float* P = Sw + p * RS2;
                ulonglong2 t0 = *(const ulonglong2*)&P[PHB + 2 * i];
                ulonglong2 t1 = *(const ulonglong2*)&P[PHB + 2 * i + 4];
                FMA4(b0[p], t0, t1, W0);
                FMA4(b1[p], t0, t1, W1);
                FMA4(b2[p], t0, t1, W2);
                FMA4(b3[p], t0, t1, W3);
            }
        }

        // ---- TP stage 1, loop A: r0 = s0@w0, p = s0@w2, r1 = t1@w1 ----
        u64 R0[NPAIR] = {0, 0, 0, 0}, PPa[NPAIR] = {0, 0, 0, 0}, R1[NPAIR] = {0, 0, 0, 0};
#pragma unroll
        for (int i = 0; i < 64; i += 4) {
            float4 w0v = *(const float4*)&w0t[lid * PADK + i];
            float4 w1v = *(const float4*)&w1t[lid * PADK + i];
            float4 w2v = *(const float4*)&w2t[lid * PADK + i];
            DUP4(W0, w0v); DUP4(W1, w1v); DUP4(W2, w2v);
#pragma unroll
            for (int p = 0; p < NPAIR; p++) {
                const float* P = Sw + p * RS2;
                ulonglong2 s0a = *(const ulonglong2*)&P[PS0 + 2 * i];
                ulonglong2 s0b = *(const ulonglong2*)&P[PS0 + 2 * i + 4];
                ulonglong2 t1a = *(const ulonglong2*)&P[PT1 + 2 * i];
                ulonglong2 t1b = *(const ulonglong2*)&P[PT1 + 2 * i + 4];
                FMA4(R0[p],  s0a, s0b, W0);
                FMA4(PPa[p], s0a, s0b, W2);
                FMA4(R1[p],  t1a, t1b, W1);
            }
        }
        // ---- TP stage 1, loop B: qk = s1k@w3 ----
        u64 Q0[NPAIR] = {0, 0, 0, 0}, Q1[NPAIR] = {0, 0, 0, 0}, Q2[NPAIR] = {0, 0, 0, 0};
#pragma unroll
        for (int i = 0; i < 64; i += 4) {
            float4 w3v = *(const float4*)&w3t[lid * PADK + i];
            DUP4(W3, w3v);
#pragma unroll
            for (int p = 0; p < NPAIR; p++) {
                const float* P = Sw + p * RS2;
                ulonglong2 u0a = *(const ulonglong2*)&P[PS1 + 2 * i];
                ulonglong2 u0b = *(const ulonglong2*)&P[PS1 + 2 * i + 4];
                ulonglong2 u1a = *(const ulonglong2*)&P[PS1 + 128 + 2 * i];
                ulonglong2 u1b = *(const ulonglong2*)&P[PS1 + 128 + 2 * i + 4];
                ulonglong2 u2a = *(const ulonglong2*)&P[PS1 + 256 + 2 * i];
                ulonglong2 u2b = *(const ulonglong2*)&P[PS1 + 256 + 2 * i + 4];
                FMA4(Q0[p], u0a, u0b, W3);
                FMA4(Q1[p], u1a, u1b, W3);
                FMA4(Q2[p], u2a, u2b, W3);
            }
        }
        __syncwarp();   // done reading s0/s1/t1 -> safe to overlay m0/m1

        // ---- build m0, m1 (packed; scales pre-folded) ----
#pragma unroll
        for (int p = 0; p < NPAIR; p++) {
            float* P = Sw + p * RS2;
            u64 Y0 = pk2(yv4[2 * p].x, yv4[2 * p + 1].x);
            u64 Y1 = pk2(yv4[2 * p].y, yv4[2 * p + 1].y);
            u64 Y2 = pk2(yv4[2 * p].z, yv4[2 * p + 1].z);
            u64 Y3 = pk2(yv4[2 * p].w, yv4[2 * p + 1].w);
            u64 pw   = f2mul(PPa[p], b2[p]);       // p * wt[64+lid]
            u64 y0wq = f2mul(Y0, b3[p]);           // y0 * wt[96+lid]
            *(u64*)&P[PS0 + 2 * lid]       = f2mul(f2mul(Y0, R0[p]), b0[p]);
            *(u64*)&P[PS0 + 64 + 2 * lid]  = f2mul(R1[p], b1[p]);
            *(u64*)&P[PS1 + 2 * lid]       = f2mul(Y1, pw);
            *(u64*)&P[PS1 + 64 + 2 * lid]  = f2mul(Q0[p], y0wq);
            *(u64*)&P[PS1 + 128 + 2 * lid] = f2mul(Y2, pw);
            *(u64*)&P[PS1 + 192 + 2 * lid] = f2mul(Q1[p], y0wq);
            *(u64*)&P[PS1 + 256 + 2 * lid] = f2mul(Y3, pw);
            *(u64*)&P[PS1 + 320 + 2 * lid] = f2mul(Q2[p], y0wq);
        }
        __syncwarp();

        // ---- final merged linears: o0 = m0@WA, o1k = m1k@WB ----
        u64 O0[NPAIR] = {0, 0, 0, 0}, O1[NPAIR] = {0, 0, 0, 0},
            O2[NPAIR] = {0, 0, 0, 0}, O3[NPAIR] = {0, 0, 0, 0};
#pragma unroll
        for (int i = 0; i < 64; i += 4) {
            float4 wav = *(const float4*)&wat[lid * PADK + i];
            float4 wbv = *(const float4*)&wbt[lid * PADK + i];
            DUP4(WA, wav); DUP4(WB, wbv);
#pragma unroll
            for (int p = 0; p < NPAIR; p++) {
                const float* P = Sw + p * RS2;
                ulonglong2 m0a = *(const ulonglong2*)&P[PS0 + 2 * i];
                ulonglong2 m0b = *(const ulonglong2*)&P[PS0 + 2 * i + 4];
                ulonglong2 k0a = *(const ulonglong2*)&P[PS1 + 2 * i];
                ulonglong2 k0b = *(const ulonglong2*)&P[PS1 + 2 * i + 4];
                ulonglong2 k1a = *(const ulonglong2*)&P[PS1 + 128 + 2 * i];
                ulonglong2 k1b = *(const ulonglong2*)&P[PS1 + 128 + 2 * i + 4];
                ulonglong2 k2a = *(const ulonglong2*)&P[PS1 + 256 + 2 * i];
                ulonglong2 k2b = *(const ulonglong2*)&P[PS1 + 256 + 2 * i + 4];
                FMA4(O0[p], m0a, m0b, WA);
                FMA4(O1[p], k0a, k0b, WB);
                FMA4(O2[p], k1a, k1b, WB);
                FMA4(O3[p], k2a, k2b, WB);
            }
        }
        __syncwarp();   // done reading m0/m1 -> safe to overlay ob

        // ---- stage + coalesced store ----
#pragma unroll
        for (int p = 0; p < NPAIR; p++) {
            float* obA = Sw + p * RS2 + PT1;
            float* obB = obA + 128;
            float xa, xb;
            upk2(O0[p], xa, xb); obA[lid] = xa;               obB[lid] = xb;
            upk2(O1[p], xa, xb); obA[32 + 3 * lid] = xa;      obB[32 + 3 * lid] = xb;
            upk2(O2[p], xa, xb); obA[33 + 3 * lid] = xa;      obB[33 + 3 * lid] = xb;
            upk2(O3[p], xa, xb); obA[34 + 3 * lid] = xa;      obB[34 + 3 * lid] = xb;
        }
        __syncwarp();
#pragma unroll
        for (int r = 0; r < 2 * NPAIR; r++) {
            const float* ob = Sw + (r >> 1) * RS2 + PT1 + (r & 1) * 128;
            ((float4*)out)[(e + r) * 32 + lid] = *(const float4*)&ob[4 * lid];
        }
        __syncwarp();
    }
}

// ---------------- launch ----------------
extern "C" void kernel_launch(void* const* d_in, const int* in_sizes, int n_in,
                              void* d_out, int out_size) {
    const float* x1a     = (const float*)d_in[0];
    const float* x1b     = (const float*)d_in[1];
    const float* x2      = (const float*)d_in[2];
    const float* scalars = (const float*)d_in[3];
    const float* w0      = (const float*)d_in[4];
    const float* w1      = (const float*)d_in[5];
    const float* w2      = (const float*)d_in[6];
    const float* w3      = (const float*)d_in[7];
    const float* Wl0     = (const float*)d_in[8];
    const float* Wl1     = (const float*)d_in[9];
    const float* Wm1     = (const float*)d_in[10];
    const float* Wm2     = (const float*)d_in[11];
    const float* Wm3     = (const float*)d_in[12];
    const float* Wf0     = (const float*)d_in[13];
    const float* Wf1     = (const float*)d_in[14];
    int n = in_sizes[0] / 128;

    cudaFuncSetAttribute(tp_main_kernel, cudaFuncAttributeMaxDynamicSharedMemorySize, SMEM_BYTES);

    prep_kernel<<<112, 256>>>(w0, w1, w2, w3, Wl0, Wl1, Wm1, Wm2, Wm3, Wf0, Wf1);
    tp_main_kernel<<<148, 256, SMEM_BYTES>>>(x1a, x1b, (const float4*)x2, scalars,
                                             (float*)d_out, n);
}